// round 4
// baseline (speedup 1.0000x reference)
#include <cuda_runtime.h>
#include <cuda_bf16.h>
#include <cstdint>

#define BATCH 8
#define SEQ   2048
#define DIM   1024
#define NST   256
#define HID   512
#define NEXP  8
#define NTOK  (BATCH*SEQ)   // 16384

// ---------------- device scratch (static, allocation-free) ----------------
__device__ __nv_bfloat16 g_xh[NTOK*DIM],      g_xl[NTOK*DIM];
__device__ __nv_bfloat16 g_Winh [NEXP*NST*DIM],   g_Winl [NEXP*NST*DIM];
__device__ __nv_bfloat16 g_Wsinh[NEXP*HID*DIM],   g_Wsinl[NEXP*HID*DIM];
__device__ __nv_bfloat16 g_Wsoh [NEXP*4*NST*HID], g_Wsol [NEXP*4*NST*HID];
__device__ __nv_bfloat16 g_Woth [NEXP*DIM*NST],   g_Wotl [NEXP*DIM*NST];
__device__ __nv_bfloat16 g_shh[NTOK*HID], g_shl[NTOK*HID];
__device__ __nv_bfloat16 g_yh [NTOK*NST], g_yl [NTOK*NST];
__device__ float g_u [NTOK*NST];
__device__ float g_a [NTOK*NST], g_bu[NTOK*NST], g_c[NTOK*NST], g_sk[NTOK*NST];
__device__ int g_list[NTOK];
__device__ int g_tileCnt[64][NEXP];
__device__ int g_tileOff[64][NEXP];
__device__ int g_eBase[NEXP];
__device__ int g_cnt[NEXP];
__device__ int g_beOff[BATCH][NEXP];
__device__ int g_beCnt[BATCH][NEXP];

__device__ __forceinline__ float sigmoidf_(float x){ return 1.f/(1.f+__expf(-x)); }

__device__ __forceinline__ uint32_t smem_u32(const void* p){
    uint32_t a;
    asm("{ .reg .u64 t; cvta.to.shared.u64 t, %1; cvt.u32.u64 %0, t; }" : "=r"(a) : "l"(p));
    return a;
}
__device__ __forceinline__ void ldsm_x4(uint32_t* r, uint32_t addr){
    asm volatile("ldmatrix.sync.aligned.m8n8.x4.shared.b16 {%0,%1,%2,%3}, [%4];"
        : "=r"(r[0]),"=r"(r[1]),"=r"(r[2]),"=r"(r[3]) : "r"(addr));
}
__device__ __forceinline__ void mma16816(float* d, const uint32_t* a, uint32_t b0, uint32_t b1){
    asm volatile("mma.sync.aligned.m16n8k16.row.col.f32.bf16.bf16.f32 "
        "{%0,%1,%2,%3}, {%4,%5,%6,%7}, {%8,%9}, {%0,%1,%2,%3};"
        : "+f"(d[0]),"+f"(d[1]),"+f"(d[2]),"+f"(d[3])
        : "r"(a[0]),"r"(a[1]),"r"(a[2]),"r"(a[3]), "r"(b0),"r"(b1));
}
__device__ __forceinline__ void cpasync16(uint32_t dst, const void* src){
    asm volatile("cp.async.cg.shared.global [%0], [%1], 16;" :: "r"(dst), "l"(src));
}
#define CP_COMMIT() asm volatile("cp.async.commit_group;" ::: "memory")
#define CP_WAIT2()  asm volatile("cp.async.wait_group 2;"  ::: "memory")

// split 2 fp32 -> bf16x2 hi + bf16x2 lo residual
__device__ __forceinline__ void split2(float a, float b, uint32_t& hi, uint32_t& lo){
    __nv_bfloat162 h = __floats2bfloat162_rn(a, b);
    float r0 = a - __bfloat162float(__low2bfloat16 (h));
    float r1 = b - __bfloat162float(__high2bfloat16(h));
    __nv_bfloat162 l = __floats2bfloat162_rn(r0, r1);
    hi = *reinterpret_cast<uint32_t*>(&h);
    lo = *reinterpret_cast<uint32_t*>(&l);
}
__device__ __forceinline__ int route_of(int tokid){
    unsigned x = (unsigned)tokid;
    x ^= x >> 16; x *= 2246822507u;
    x ^= x >> 13; x *= 3266489909u;
    x ^= x >> 16;
    return (int)(x & 7u);
}

// ---------------- conversion: fp32 -> bf16 hi/lo ----------------
__global__ void __launch_bounds__(256)
cvt_kernel(const float* __restrict__ src, __nv_bfloat16* __restrict__ dh,
           __nv_bfloat16* __restrict__ dl, int n4)
{
    int i = blockIdx.x*blockDim.x + threadIdx.x;
    if (i >= n4) return;
    float4 v = reinterpret_cast<const float4*>(src)[i];
    uint32_t h0,l0,h1,l1;
    split2(v.x, v.y, h0, l0);
    split2(v.z, v.w, h1, l1);
    reinterpret_cast<uint2*>(dh)[i] = make_uint2(h0, h1);
    reinterpret_cast<uint2*>(dl)[i] = make_uint2(l0, l1);
}

// ---------------- deterministic routing (count / offset / place) ----------
__global__ void count_kernel(const int* __restrict__ tok){
    int blk = blockIdx.x, tid = threadIdx.x, wid = tid>>5, lane = tid&31;
    int r = route_of(tok[blk*256 + tid]);
    __shared__ int wcnt[8][8];
    unsigned m[8];
    #pragma unroll
    for (int e = 0; e < 8; e++) m[e] = __ballot_sync(0xffffffffu, r == e);
    if (lane < 8) wcnt[wid][lane] = __popc(m[lane]);
    __syncthreads();
    if (tid < 8){
        int s = 0;
        #pragma unroll
        for (int w = 0; w < 8; w++) s += wcnt[w][tid];
        g_tileCnt[blk][tid] = s;
    }
}
__global__ void offset_kernel(){
    __shared__ int tot[8];
    int tid = threadIdx.x;
    if (tid < 8){
        int run = 0;
        for (int t = 0; t < 64; t++){ g_tileOff[t][tid] = run; run += g_tileCnt[t][tid]; }
        tot[tid] = run;
    }
    __syncthreads();
    if (tid == 0){
        int base = 0;
        for (int e = 0; e < 8; e++){ g_eBase[e] = base; g_cnt[e] = tot[e]; base += tot[e]; }
    }
    __syncthreads();
    if (tid < 8){
        for (int t = 0; t < 64; t++) g_tileOff[t][tid] += g_eBase[tid];
        for (int b = 0; b < 8; b++){
            int s = 0;
            for (int k = 0; k < 8; k++) s += g_tileCnt[b*8+k][tid];
            g_beOff[b][tid] = g_tileOff[b*8][tid];
            g_beCnt[b][tid] = s;
        }
    }
}
__global__ void place_kernel(const int* __restrict__ tok){
    int blk = blockIdx.x, tid = threadIdx.x, wid = tid>>5, lane = tid&31;
    int t = blk*256 + tid;
    int r = route_of(tok[t]);
    __shared__ int wcnt[8][8];
    unsigned m[8];
    #pragma unroll
    for (int e = 0; e < 8; e++) m[e] = __ballot_sync(0xffffffffu, r == e);
    if (lane < 8) wcnt[wid][lane] = __popc(m[lane]);
    __syncthreads();
    int base = 0;
    for (int w = 0; w < wid; w++) base += wcnt[w][r];
    int rank = base + __popc(m[r] & ((1u << lane) - 1u));
    g_list[g_tileOff[blk][r] + rank] = t;
}

// ---------------- grouped GEMM (mma.sync bf16x3, cp.async 3-stage) --------
// C = A . W[e]^T with pre-split bf16 hi/lo operands.
// MODE: 0 u, 1 silu->sh(bf16), 2 gates, 3 out proj.  GATHER: A row via g_list
#define KC     32
#define SSTR   80
#define STILE  (128*SSTR)     // 10240
#define STAGE  (4*STILE)      // 40960  (Ah|Al|Bh|Bl)
#define GSMEM  (3*STAGE)      // 122880

template<int MODE, int GATHER>
__global__ void __launch_bounds__(256)
gemm_mma(const __nv_bfloat16* __restrict__ Ah, const __nv_bfloat16* __restrict__ Al,
         const __nv_bfloat16* __restrict__ Wh, const __nv_bfloat16* __restrict__ Wl,
         const float* __restrict__ dparam, float* __restrict__ outp,
         int lda, int K, int nout)
{
    const int e   = blockIdx.z;
    const int cnt = g_cnt[e];
    const int m0  = blockIdx.x * 128;
    if (m0 >= cnt) return;
    const int n0  = blockIdx.y * 128;
    const int posBase = g_eBase[e];
    Wh += (size_t)e * nout * K;
    Wl += (size_t)e * nout * K;

    extern __shared__ __align__(16) char sm[];
    __shared__ int s_tok[128];

    const int tid  = threadIdx.x;
    const int wid  = tid >> 5;
    const int lane = tid & 31;

    if (tid < 128){
        int m  = m0 + tid;
        int mm = m < cnt ? m : cnt - 1;
        s_tok[tid] = GATHER ? g_list[posBase + mm] : (posBase + mm);
    }
    __syncthreads();

    // loader: thread -> row lrow, 32B half-row lk (elements)
    const int lrow = tid >> 1;
    const int lk   = (tid & 1) * 16;
    const __nv_bfloat16* apH = Ah + (size_t)s_tok[lrow]*lda + lk;
    const __nv_bfloat16* apL = Al + (size_t)s_tok[lrow]*lda + lk;
    const __nv_bfloat16* bpH = Wh + (size_t)(n0 + lrow)*K + lk;
    const __nv_bfloat16* bpL = Wl + (size_t)(n0 + lrow)*K + lk;

    const uint32_t sb   = smem_u32(sm);
    const uint32_t sdst = sb + (uint32_t)(lrow*SSTR + lk*2);

    auto issue_stage = [&](int st, int k0){
        uint32_t d = sdst + st*STAGE;
        cpasync16(d,              apH + k0);
        cpasync16(d + 16,         apH + k0 + 8);
        cpasync16(d +   STILE,    apL + k0);
        cpasync16(d +   STILE+16, apL + k0 + 8);
        cpasync16(d + 2*STILE,    bpH + k0);
        cpasync16(d + 2*STILE+16, bpH + k0 + 8);
        cpasync16(d + 3*STILE,    bpL + k0);
        cpasync16(d + 3*STILE+16, bpL + k0 + 8);
        CP_COMMIT();
    };

    const int wm = wid & 1, wn = wid >> 1;
    const uint32_t a_base = sb + (uint32_t)((wm*64 + (lane & 15))*SSTR + (lane >> 4)*16);
    const uint32_t b_base = sb + 2*STILE +
        (uint32_t)((wn*32 + (lane >> 4)*8 + (lane & 7))*SSTR + ((lane >> 3) & 1)*16);

    float acc[4][4][4];
    #pragma unroll
    for (int mi=0;mi<4;mi++)
        #pragma unroll
        for (int ni=0;ni<4;ni++)
            #pragma unroll
            for (int q=0;q<4;q++) acc[mi][ni][q]=0.f;

    const int NC = K >> 5;
    issue_stage(0, 0);
    issue_stage(1, 32);

    for (int c = 0; c < NC; c++){
        if (c + 2 < NC) issue_stage((c + 2) % 3, (c + 2) << 5);
        else            CP_COMMIT();                 // keep group accounting uniform
        CP_WAIT2();
        __syncthreads();

        const uint32_t ab = a_base + (c % 3)*STAGE;
        const uint32_t bb = b_base + (c % 3)*STAGE;
        #pragma unroll
        for (int ks = 0; ks < 2; ks++){
            uint32_t ah[4][4], al[4][4], bh[2][4], bl[2][4];
            #pragma unroll
            for (int mi = 0; mi < 4; mi++){
                uint32_t ad = ab + mi*16*SSTR + ks*32;
                ldsm_x4(ah[mi], ad);
                ldsm_x4(al[mi], ad + STILE);
            }
            #pragma unroll
            for (int np = 0; np < 2; np++){
                uint32_t bd = bb + np*16*SSTR + ks*32;
                ldsm_x4(bh[np], bd);
                ldsm_x4(bl[np], bd + STILE);
            }
            #pragma unroll
            for (int mi = 0; mi < 4; mi++)
                #pragma unroll
                for (int ni = 0; ni < 4; ni++){
                    const int np = ni >> 1, h = (ni & 1)*2;
                    mma16816(acc[mi][ni], ah[mi], bh[np][h], bh[np][h+1]);
                    mma16816(acc[mi][ni], ah[mi], bl[np][h], bl[np][h+1]);
                    mma16816(acc[mi][ni], al[mi], bh[np][h], bh[np][h+1]);
                }
        }
        __syncthreads();
    }

    // ---- epilogue
    const int sec = (MODE == 2) ? (n0 >> 8) : 0;
    #pragma unroll
    for (int mi = 0; mi < 4; mi++){
        const int rt0 = wm*64 + mi*16 + (lane >> 2);
        #pragma unroll
        for (int hf = 0; hf < 2; hf++){
            const int rt = rt0 + hf*8;
            const int m  = m0 + rt;
            if (m >= cnt) continue;
            const int pos = posBase + m;
            #pragma unroll
            for (int ni = 0; ni < 4; ni++){
                float v0 = acc[mi][ni][hf*2], v1 = acc[mi][ni][hf*2+1];
                const int col = n0 + wn*32 + (ni>>1)*16 + (ni&1)*8 + (lane&3)*2;
                if (MODE == 0){
                    *(float2*)(g_u + (size_t)pos*NST + col) = make_float2(v0, v1);
                } else if (MODE == 1){
                    float s0 = v0*sigmoidf_(v0), s1 = v1*sigmoidf_(v1);
                    uint32_t hi, lo; split2(s0, s1, hi, lo);
                    *reinterpret_cast<uint32_t*>(g_shh + (size_t)pos*HID + col) = hi;
                    *reinterpret_cast<uint32_t*>(g_shl + (size_t)pos*HID + col) = lo;
                } else if (MODE == 2){
                    const int off = col & 255;
                    const size_t base = (size_t)pos*NST + off;
                    if (sec == 0){
                        *(float2*)(g_a + base) = make_float2(sigmoidf_(v0), sigmoidf_(v1));
                    } else if (sec == 1){
                        float2 u2 = *(const float2*)(g_u + base);
                        *(float2*)(g_bu + base) = make_float2(tanhf(v0)*u2.x, tanhf(v1)*u2.y);
                    } else if (sec == 2){
                        *(float2*)(g_c + base) = make_float2(tanhf(v0), tanhf(v1));
                    } else {
                        float2 u2 = *(const float2*)(g_u + base);
                        float2 d2 = *(const float2*)(dparam + e*NST + off);
                        *(float2*)(g_sk + base) =
                            make_float2(sigmoidf_(v0)*d2.x*u2.x, sigmoidf_(v1)*d2.y*u2.y);
                    }
                } else {
                    const int tok = g_list[pos];
                    *(float2*)(outp + (size_t)tok*DIM + col) = make_float2(v0, v1);
                }
            }
        }
    }
}

// ---------------- sequential scan, compact streaming ----------------
__global__ void __launch_bounds__(256)
scan_kernel()
{
    const int b = blockIdx.x, e = blockIdx.y, tid = threadIdx.x;
    const int pos0 = g_beOff[b][e];
    const int n    = g_beCnt[b][e];

    float a[2][4], bu[2][4], cc[2][4], sk[2][4];
    #pragma unroll
    for (int j = 0; j < 4; j++){
        bool v = j < n;
        size_t idx = ((size_t)(pos0 + (v ? j : 0)))*NST + tid;
        a [0][j] = v ? g_a [idx] : 0.f;
        bu[0][j] = v ? g_bu[idx] : 0.f;
        cc[0][j] = v ? g_c [idx] : 0.f;
        sk[0][j] = v ? g_sk[idx] : 0.f;
    }

    float h = 0.f;
    int cur = 0;
    for (int base = 0; base < n; base += 4){
        const int nxt = cur ^ 1;
        #pragma unroll
        for (int j = 0; j < 4; j++){
            int i = base + 4 + j;
            if (i < n){
                size_t idx = ((size_t)(pos0 + i))*NST + tid;
                a [nxt][j] = g_a [idx];
                bu[nxt][j] = g_bu[idx];
                cc[nxt][j] = g_c [idx];
                sk[nxt][j] = g_sk[idx];
            }
        }
        #pragma unroll
        for (int j = 0; j < 4; j++){
            int i = base + j;
            if (i < n){
                h = fmaf(a[cur][j], h, bu[cur][j]);
                float y = fmaf(cc[cur][j], h, sk[cur][j]);
                size_t idx = ((size_t)(pos0 + i))*NST + tid;
                __nv_bfloat16 yh = __float2bfloat16(y);
                g_yh[idx] = yh;
                g_yl[idx] = __float2bfloat16(y - __bfloat162float(yh));
            }
        }
        cur = nxt;
    }
}

// ---------------- launch ----------------
extern "C" void kernel_launch(void* const* d_in, const int* in_sizes, int n_in,
                              void* d_out, int out_size)
{
    const float* x     = (const float*)d_in[0];
    const int*   tok   = (const int*)  d_in[1];
    const float* Win   = (const float*)d_in[2];
    const float* Wsin  = (const float*)d_in[3];
    const float* Wsout = (const float*)d_in[4];
    const float* Wout  = (const float*)d_in[5];
    const float* dpar  = (const float*)d_in[6];
    float* outp = (float*)d_out;
    (void)in_sizes; (void)n_in; (void)out_size;

    cudaFuncSetAttribute(gemm_mma<0,1>, cudaFuncAttributeMaxDynamicSharedMemorySize, GSMEM);
    cudaFuncSetAttribute(gemm_mma<1,1>, cudaFuncAttributeMaxDynamicSharedMemorySize, GSMEM);
    cudaFuncSetAttribute(gemm_mma<2,0>, cudaFuncAttributeMaxDynamicSharedMemorySize, GSMEM);
    cudaFuncSetAttribute(gemm_mma<3,0>, cudaFuncAttributeMaxDynamicSharedMemorySize, GSMEM);

    __nv_bfloat16 *xh, *xl, *winh, *winl, *wsih, *wsil, *wsoh, *wsol, *woth, *wotl;
    __nv_bfloat16 *shh, *shl, *yh, *yl;
    cudaGetSymbolAddress((void**)&xh,  g_xh);   cudaGetSymbolAddress((void**)&xl,  g_xl);
    cudaGetSymbolAddress((void**)&winh,g_Winh); cudaGetSymbolAddress((void**)&winl,g_Winl);
    cudaGetSymbolAddress((void**)&wsih,g_Wsinh);cudaGetSymbolAddress((void**)&wsil,g_Wsinl);
    cudaGetSymbolAddress((void**)&wsoh,g_Wsoh); cudaGetSymbolAddress((void**)&wsol,g_Wsol);
    cudaGetSymbolAddress((void**)&woth,g_Woth); cudaGetSymbolAddress((void**)&wotl,g_Wotl);
    cudaGetSymbolAddress((void**)&shh, g_shh);  cudaGetSymbolAddress((void**)&shl, g_shl);
    cudaGetSymbolAddress((void**)&yh,  g_yh);   cudaGetSymbolAddress((void**)&yl,  g_yl);

    // conversions
    cvt_kernel<<<(NTOK*DIM/4 + 255)/256, 256>>>(x,     xh,   xl,   NTOK*DIM/4);
    cvt_kernel<<<(NEXP*NST*DIM/4 + 255)/256, 256>>>(Win,   winh, winl, NEXP*NST*DIM/4);
    cvt_kernel<<<(NEXP*HID*DIM/4 + 255)/256, 256>>>(Wsin,  wsih, wsil, NEXP*HID*DIM/4);
    cvt_kernel<<<(NEXP*4*NST*HID/4 + 255)/256, 256>>>(Wsout, wsoh, wsol, NEXP*4*NST*HID/4);
    cvt_kernel<<<(NEXP*DIM*NST/4 + 255)/256, 256>>>(Wout,  woth, wotl, NEXP*DIM*NST/4);

    // deterministic routing
    count_kernel <<<64, 256>>>(tok);
    offset_kernel<<<1, 256>>>();
    place_kernel <<<64, 256>>>(tok);

    dim3 blk(256);
    // u = x . Win^T
    gemm_mma<0,1><<<dim3(20, 2, NEXP), blk, GSMEM>>>(xh, xl, winh, winl, nullptr, nullptr, DIM, DIM, NST);
    // sh = silu(x . Wsin^T)
    gemm_mma<1,1><<<dim3(20, 4, NEXP), blk, GSMEM>>>(xh, xl, wsih, wsil, nullptr, nullptr, DIM, DIM, HID);
    // gates = sh . Wsout^T
    gemm_mma<2,0><<<dim3(20, 8, NEXP), blk, GSMEM>>>(shh, shl, wsoh, wsol, dpar, nullptr, HID, HID, 4*NST);
    // recurrence
    scan_kernel<<<dim3(BATCH, NEXP), 256>>>();
    // out = y . Wout^T
    gemm_mma<3,0><<<dim3(20, 8, NEXP), blk, GSMEM>>>(yh, yl, woth, wotl, nullptr, outp, NST, NST, DIM);
}

// round 5
// speedup vs baseline: 1.0326x; 1.0326x over previous
#include <cuda_runtime.h>
#include <cuda_bf16.h>
#include <cstdint>

#define BATCH 8
#define SEQ   2048
#define DIM   1024
#define NST   256
#define HID   512
#define NEXP  8
#define NTOK  (BATCH*SEQ)   // 16384

// ---------------- device scratch (static, allocation-free) ----------------
__device__ __nv_bfloat16 g_xh[NTOK*DIM],      g_xl[NTOK*DIM];
__device__ __nv_bfloat16 g_Winh [NEXP*NST*DIM],   g_Winl [NEXP*NST*DIM];
__device__ __nv_bfloat16 g_Wsinh[NEXP*HID*DIM],   g_Wsinl[NEXP*HID*DIM];
__device__ __nv_bfloat16 g_Wsoh [NEXP*4*NST*HID], g_Wsol [NEXP*4*NST*HID];
__device__ __nv_bfloat16 g_Woth [NEXP*DIM*NST],   g_Wotl [NEXP*DIM*NST];
__device__ __nv_bfloat16 g_shh[NTOK*HID], g_shl[NTOK*HID];
__device__ __nv_bfloat16 g_yh [NTOK*NST], g_yl [NTOK*NST];
__device__ float g_u [NTOK*NST];
__device__ float g_a [NTOK*NST], g_bu[NTOK*NST], g_c[NTOK*NST], g_sk[NTOK*NST];
__device__ int g_list[NTOK];
__device__ int g_tileCnt[64][NEXP];
__device__ int g_tileOff[64][NEXP];
__device__ int g_eBase[NEXP];
__device__ int g_cnt[NEXP];
__device__ int g_beOff[BATCH][NEXP];
__device__ int g_beCnt[BATCH][NEXP];

__device__ __forceinline__ float sigmoidf_(float x){ return 1.f/(1.f+__expf(-x)); }

__device__ __forceinline__ uint32_t smem_u32(const void* p){
    uint32_t a;
    asm("{ .reg .u64 t; cvta.to.shared.u64 t, %1; cvt.u32.u64 %0, t; }" : "=r"(a) : "l"(p));
    return a;
}
__device__ __forceinline__ void ldsm_x4(uint32_t* r, uint32_t addr){
    asm volatile("ldmatrix.sync.aligned.m8n8.x4.shared.b16 {%0,%1,%2,%3}, [%4];"
        : "=r"(r[0]),"=r"(r[1]),"=r"(r[2]),"=r"(r[3]) : "r"(addr));
}
__device__ __forceinline__ void mma16816(float* d, const uint32_t* a, uint32_t b0, uint32_t b1){
    asm volatile("mma.sync.aligned.m16n8k16.row.col.f32.bf16.bf16.f32 "
        "{%0,%1,%2,%3}, {%4,%5,%6,%7}, {%8,%9}, {%0,%1,%2,%3};"
        : "+f"(d[0]),"+f"(d[1]),"+f"(d[2]),"+f"(d[3])
        : "r"(a[0]),"r"(a[1]),"r"(a[2]),"r"(a[3]), "r"(b0),"r"(b1));
}

// split 2 fp32 -> bf16x2 hi + bf16x2 lo residual
__device__ __forceinline__ void split2(float a, float b, uint32_t& hi, uint32_t& lo){
    __nv_bfloat162 h = __floats2bfloat162_rn(a, b);
    float r0 = a - __bfloat162float(__low2bfloat16 (h));
    float r1 = b - __bfloat162float(__high2bfloat16(h));
    __nv_bfloat162 l = __floats2bfloat162_rn(r0, r1);
    hi = *reinterpret_cast<uint32_t*>(&h);
    lo = *reinterpret_cast<uint32_t*>(&l);
}
__device__ __forceinline__ int route_of(int tokid){
    unsigned x = (unsigned)tokid;
    x ^= x >> 16; x *= 2246822507u;
    x ^= x >> 13; x *= 3266489909u;
    x ^= x >> 16;
    return (int)(x & 7u);
}

// ---------------- conversion: fp32 -> bf16 hi/lo ----------------
__global__ void __launch_bounds__(256)
cvt_kernel(const float* __restrict__ src, __nv_bfloat16* __restrict__ dh,
           __nv_bfloat16* __restrict__ dl, int n4)
{
    int i = blockIdx.x*blockDim.x + threadIdx.x;
    if (i >= n4) return;
    float4 v = reinterpret_cast<const float4*>(src)[i];
    uint32_t h0,l0,h1,l1;
    split2(v.x, v.y, h0, l0);
    split2(v.z, v.w, h1, l1);
    reinterpret_cast<uint2*>(dh)[i] = make_uint2(h0, h1);
    reinterpret_cast<uint2*>(dl)[i] = make_uint2(l0, l1);
}

// ---------------- deterministic routing (count / offset / place) ----------
__global__ void count_kernel(const int* __restrict__ tok){
    int blk = blockIdx.x, tid = threadIdx.x, wid = tid>>5, lane = tid&31;
    int r = route_of(tok[blk*256 + tid]);
    __shared__ int wcnt[8][8];
    unsigned m[8];
    #pragma unroll
    for (int e = 0; e < 8; e++) m[e] = __ballot_sync(0xffffffffu, r == e);
    if (lane < 8) wcnt[wid][lane] = __popc(m[lane]);
    __syncthreads();
    if (tid < 8){
        int s = 0;
        #pragma unroll
        for (int w = 0; w < 8; w++) s += wcnt[w][tid];
        g_tileCnt[blk][tid] = s;
    }
}
__global__ void offset_kernel(){
    __shared__ int tot[8];
    int tid = threadIdx.x;
    if (tid < 8){
        int run = 0;
        for (int t = 0; t < 64; t++){ g_tileOff[t][tid] = run; run += g_tileCnt[t][tid]; }
        tot[tid] = run;
    }
    __syncthreads();
    if (tid == 0){
        int base = 0;
        for (int e = 0; e < 8; e++){ g_eBase[e] = base; g_cnt[e] = tot[e]; base += tot[e]; }
    }
    __syncthreads();
    if (tid < 8){
        for (int t = 0; t < 64; t++) g_tileOff[t][tid] += g_eBase[tid];
        for (int b = 0; b < 8; b++){
            int s = 0;
            for (int k = 0; k < 8; k++) s += g_tileCnt[b*8+k][tid];
            g_beOff[b][tid] = g_tileOff[b*8][tid];
            g_beCnt[b][tid] = s;
        }
    }
}
__global__ void place_kernel(const int* __restrict__ tok){
    int blk = blockIdx.x, tid = threadIdx.x, wid = tid>>5, lane = tid&31;
    int t = blk*256 + tid;
    int r = route_of(tok[t]);
    __shared__ int wcnt[8][8];
    unsigned m[8];
    #pragma unroll
    for (int e = 0; e < 8; e++) m[e] = __ballot_sync(0xffffffffu, r == e);
    if (lane < 8) wcnt[wid][lane] = __popc(m[lane]);
    __syncthreads();
    int base = 0;
    for (int w = 0; w < wid; w++) base += wcnt[w][r];
    int rank = base + __popc(m[r] & ((1u << lane) - 1u));
    g_list[g_tileOff[blk][r] + rank] = t;
}

// ---------------- grouped GEMM (mma.sync bf16x3, LDG->STS double buffer) ---
// C = A . W[e]^T with pre-split bf16 hi/lo operands.
// MODE: 0 u, 1 silu->sh(bf16), 2 gates, 3 out proj.  GATHER: A row via g_list
#define SSTR   80
#define STILE  (128*SSTR)     // 10240
#define STAGE  (4*STILE)      // 40960  (Ah|Al|Bh|Bl)
#define GSMEM  (2*STAGE)      // 81920

template<int MODE, int GATHER>
__global__ void __launch_bounds__(256)
gemm_mma(const __nv_bfloat16* __restrict__ Ah, const __nv_bfloat16* __restrict__ Al,
         const __nv_bfloat16* __restrict__ Wh, const __nv_bfloat16* __restrict__ Wl,
         const float* __restrict__ dparam, float* __restrict__ outp,
         int lda, int K, int nout)
{
    const int e   = blockIdx.z;
    const int cnt = g_cnt[e];
    const int m0  = blockIdx.x * 128;
    if (m0 >= cnt) return;
    const int n0  = blockIdx.y * 128;
    const int posBase = g_eBase[e];
    Wh += (size_t)e * nout * K;
    Wl += (size_t)e * nout * K;

    extern __shared__ __align__(16) char sm[];
    __shared__ int s_tok[128];

    const int tid  = threadIdx.x;
    const int wid  = tid >> 5;
    const int lane = tid & 31;

    if (tid < 128){
        int m  = m0 + tid;
        int mm = m < cnt ? m : cnt - 1;
        s_tok[tid] = GATHER ? g_list[posBase + mm] : (posBase + mm);
    }
    __syncthreads();

    // loader: thread -> row (tid>>1), 32B segment (tid&1)
    const int lrow = tid >> 1;
    const int lk   = (tid & 1) * 16;     // element offset within 32-elem chunk row
    const __nv_bfloat16* apH = Ah + (size_t)s_tok[lrow]*lda + lk;
    const __nv_bfloat16* apL = Al + (size_t)s_tok[lrow]*lda + lk;
    const __nv_bfloat16* bpH = Wh + (size_t)(n0 + lrow)*K + lk;
    const __nv_bfloat16* bpL = Wl + (size_t)(n0 + lrow)*K + lk;
    char* sdst = sm + lrow*SSTR + lk*2;

    const uint32_t sb = smem_u32(sm);
    const int wm = wid & 1, wn = wid >> 1;
    const uint32_t a_base = sb + (uint32_t)((wm*64 + (lane & 15))*SSTR + (lane >> 4)*16);
    const uint32_t b_base = sb + 2*STILE +
        (uint32_t)((wn*32 + (lane >> 4)*8 + (lane & 7))*SSTR + ((lane >> 3) & 1)*16);

    float acc[4][4][4];
    #pragma unroll
    for (int mi=0;mi<4;mi++)
        #pragma unroll
        for (int ni=0;ni<4;ni++)
            #pragma unroll
            for (int q=0;q<4;q++) acc[mi][ni][q]=0.f;

    const int NC = K >> 5;

    uint4 r[8];
    {
        r[0]=*(const uint4*)(apH);   r[1]=*(const uint4*)(apH+8);
        r[2]=*(const uint4*)(apL);   r[3]=*(const uint4*)(apL+8);
        r[4]=*(const uint4*)(bpH);   r[5]=*(const uint4*)(bpH+8);
        r[6]=*(const uint4*)(bpL);   r[7]=*(const uint4*)(bpL+8);
    }

    for (int c = 0; c < NC; c++){
        __syncthreads();   // buffer (c&1) free: MMA of chunk c-2 done
        {
            char* d = sdst + (c & 1)*STAGE;
            *(uint4*)(d)            = r[0];
            *(uint4*)(d+16)         = r[1];
            *(uint4*)(d+STILE)      = r[2];
            *(uint4*)(d+STILE+16)   = r[3];
            *(uint4*)(d+2*STILE)    = r[4];
            *(uint4*)(d+2*STILE+16) = r[5];
            *(uint4*)(d+3*STILE)    = r[6];
            *(uint4*)(d+3*STILE+16) = r[7];
        }
        if (c + 1 < NC){
            const int k1 = (c + 1) << 5;
            r[0]=*(const uint4*)(apH+k1);   r[1]=*(const uint4*)(apH+k1+8);
            r[2]=*(const uint4*)(apL+k1);   r[3]=*(const uint4*)(apL+k1+8);
            r[4]=*(const uint4*)(bpH+k1);   r[5]=*(const uint4*)(bpH+k1+8);
            r[6]=*(const uint4*)(bpL+k1);   r[7]=*(const uint4*)(bpL+k1+8);
        }
        __syncthreads();   // STS of chunk c visible

        const uint32_t ab = a_base + (c & 1)*STAGE;
        const uint32_t bb = b_base + (c & 1)*STAGE;
        #pragma unroll
        for (int ks = 0; ks < 2; ks++){
            uint32_t ah[4][4], al[4][4], bh[2][4], bl[2][4];
            #pragma unroll
            for (int mi = 0; mi < 4; mi++){
                uint32_t ad = ab + mi*16*SSTR + ks*32;
                ldsm_x4(ah[mi], ad);
                ldsm_x4(al[mi], ad + STILE);
            }
            #pragma unroll
            for (int np = 0; np < 2; np++){
                uint32_t bd = bb + np*16*SSTR + ks*32;
                ldsm_x4(bh[np], bd);
                ldsm_x4(bl[np], bd + STILE);
            }
            #pragma unroll
            for (int mi = 0; mi < 4; mi++)
                #pragma unroll
                for (int ni = 0; ni < 4; ni++){
                    const int np = ni >> 1, h = (ni & 1)*2;
                    mma16816(acc[mi][ni], ah[mi], bh[np][h], bh[np][h+1]);
                    mma16816(acc[mi][ni], ah[mi], bl[np][h], bl[np][h+1]);
                    mma16816(acc[mi][ni], al[mi], bh[np][h], bh[np][h+1]);
                }
        }
    }

    // ---- epilogue
    const int sec = (MODE == 2) ? (n0 >> 8) : 0;
    #pragma unroll
    for (int mi = 0; mi < 4; mi++){
        const int rt0 = wm*64 + mi*16 + (lane >> 2);
        #pragma unroll
        for (int hf = 0; hf < 2; hf++){
            const int rt = rt0 + hf*8;
            const int m  = m0 + rt;
            if (m >= cnt) continue;
            const int pos = posBase + m;
            #pragma unroll
            for (int ni = 0; ni < 4; ni++){
                float v0 = acc[mi][ni][hf*2], v1 = acc[mi][ni][hf*2+1];
                const int col = n0 + wn*32 + (ni>>1)*16 + (ni&1)*8 + (lane&3)*2;
                if (MODE == 0){
                    *(float2*)(g_u + (size_t)pos*NST + col) = make_float2(v0, v1);
                } else if (MODE == 1){
                    float s0 = v0*sigmoidf_(v0), s1 = v1*sigmoidf_(v1);
                    uint32_t hi, lo; split2(s0, s1, hi, lo);
                    *reinterpret_cast<uint32_t*>(g_shh + (size_t)pos*HID + col) = hi;
                    *reinterpret_cast<uint32_t*>(g_shl + (size_t)pos*HID + col) = lo;
                } else if (MODE == 2){
                    const int off = col & 255;
                    const size_t base = (size_t)pos*NST + off;
                    if (sec == 0){
                        *(float2*)(g_a + base) = make_float2(sigmoidf_(v0), sigmoidf_(v1));
                    } else if (sec == 1){
                        float2 u2 = *(const float2*)(g_u + base);
                        *(float2*)(g_bu + base) = make_float2(tanhf(v0)*u2.x, tanhf(v1)*u2.y);
                    } else if (sec == 2){
                        *(float2*)(g_c + base) = make_float2(tanhf(v0), tanhf(v1));
                    } else {
                        float2 u2 = *(const float2*)(g_u + base);
                        float2 d2 = *(const float2*)(dparam + e*NST + off);
                        *(float2*)(g_sk + base) =
                            make_float2(sigmoidf_(v0)*d2.x*u2.x, sigmoidf_(v1)*d2.y*u2.y);
                    }
                } else {
                    const int tok = g_list[pos];
                    *(float2*)(outp + (size_t)tok*DIM + col) = make_float2(v0, v1);
                }
            }
        }
    }
}

// ---------------- sequential scan, compact streaming ----------------
__global__ void __launch_bounds__(256)
scan_kernel()
{
    const int b = blockIdx.x, e = blockIdx.y, tid = threadIdx.x;
    const int pos0 = g_beOff[b][e];
    const int n    = g_beCnt[b][e];

    float a[2][4], bu[2][4], cc[2][4], sk[2][4];
    #pragma unroll
    for (int j = 0; j < 4; j++){
        bool v = j < n;
        size_t idx = ((size_t)(pos0 + (v ? j : 0)))*NST + tid;
        a [0][j] = v ? g_a [idx] : 0.f;
        bu[0][j] = v ? g_bu[idx] : 0.f;
        cc[0][j] = v ? g_c [idx] : 0.f;
        sk[0][j] = v ? g_sk[idx] : 0.f;
    }

    float h = 0.f;
    int cur = 0;
    for (int base = 0; base < n; base += 4){
        const int nxt = cur ^ 1;
        #pragma unroll
        for (int j = 0; j < 4; j++){
            int i = base + 4 + j;
            if (i < n){
                size_t idx = ((size_t)(pos0 + i))*NST + tid;
                a [nxt][j] = g_a [idx];
                bu[nxt][j] = g_bu[idx];
                cc[nxt][j] = g_c [idx];
                sk[nxt][j] = g_sk[idx];
            }
        }
        #pragma unroll
        for (int j = 0; j < 4; j++){
            int i = base + j;
            if (i < n){
                h = fmaf(a[cur][j], h, bu[cur][j]);
                float y = fmaf(cc[cur][j], h, sk[cur][j]);
                size_t idx = ((size_t)(pos0 + i))*NST + tid;
                __nv_bfloat16 yh = __float2bfloat16(y);
                g_yh[idx] = yh;
                g_yl[idx] = __float2bfloat16(y - __bfloat162float(yh));
            }
        }
        cur = nxt;
    }
}

// ---------------- launch ----------------
extern "C" void kernel_launch(void* const* d_in, const int* in_sizes, int n_in,
                              void* d_out, int out_size)
{
    const float* x     = (const float*)d_in[0];
    const int*   tok   = (const int*)  d_in[1];
    const float* Win   = (const float*)d_in[2];
    const float* Wsin  = (const float*)d_in[3];
    const float* Wsout = (const float*)d_in[4];
    const float* Wout  = (const float*)d_in[5];
    const float* dpar  = (const float*)d_in[6];
    float* outp = (float*)d_out;
    (void)in_sizes; (void)n_in; (void)out_size;

    cudaFuncSetAttribute(gemm_mma<0,1>, cudaFuncAttributeMaxDynamicSharedMemorySize, GSMEM);
    cudaFuncSetAttribute(gemm_mma<1,1>, cudaFuncAttributeMaxDynamicSharedMemorySize, GSMEM);
    cudaFuncSetAttribute(gemm_mma<2,0>, cudaFuncAttributeMaxDynamicSharedMemorySize, GSMEM);
    cudaFuncSetAttribute(gemm_mma<3,0>, cudaFuncAttributeMaxDynamicSharedMemorySize, GSMEM);

    __nv_bfloat16 *xh, *xl, *winh, *winl, *wsih, *wsil, *wsoh, *wsol, *woth, *wotl;
    __nv_bfloat16 *shh, *shl, *yh, *yl;
    cudaGetSymbolAddress((void**)&xh,  g_xh);   cudaGetSymbolAddress((void**)&xl,  g_xl);
    cudaGetSymbolAddress((void**)&winh,g_Winh); cudaGetSymbolAddress((void**)&winl,g_Winl);
    cudaGetSymbolAddress((void**)&wsih,g_Wsinh);cudaGetSymbolAddress((void**)&wsil,g_Wsinl);
    cudaGetSymbolAddress((void**)&wsoh,g_Wsoh); cudaGetSymbolAddress((void**)&wsol,g_Wsol);
    cudaGetSymbolAddress((void**)&woth,g_Woth); cudaGetSymbolAddress((void**)&wotl,g_Wotl);
    cudaGetSymbolAddress((void**)&shh, g_shh);  cudaGetSymbolAddress((void**)&shl, g_shl);
    cudaGetSymbolAddress((void**)&yh,  g_yh);   cudaGetSymbolAddress((void**)&yl,  g_yl);

    // conversions
    cvt_kernel<<<(NTOK*DIM/4 + 255)/256, 256>>>(x,     xh,   xl,   NTOK*DIM/4);
    cvt_kernel<<<(NEXP*NST*DIM/4 + 255)/256, 256>>>(Win,   winh, winl, NEXP*NST*DIM/4);
    cvt_kernel<<<(NEXP*HID*DIM/4 + 255)/256, 256>>>(Wsin,  wsih, wsil, NEXP*HID*DIM/4);
    cvt_kernel<<<(NEXP*4*NST*HID/4 + 255)/256, 256>>>(Wsout, wsoh, wsol, NEXP*4*NST*HID/4);
    cvt_kernel<<<(NEXP*DIM*NST/4 + 255)/256, 256>>>(Wout,  woth, wotl, NEXP*DIM*NST/4);

    // deterministic routing
    count_kernel <<<64, 256>>>(tok);
    offset_kernel<<<1, 256>>>();
    place_kernel <<<64, 256>>>(tok);

    dim3 blk(256);
    // u = x . Win^T
    gemm_mma<0,1><<<dim3(20, 2, NEXP), blk, GSMEM>>>(xh, xl, winh, winl, nullptr, nullptr, DIM, DIM, NST);
    // sh = silu(x . Wsin^T)
    gemm_mma<1,1><<<dim3(20, 4, NEXP), blk, GSMEM>>>(xh, xl, wsih, wsil, nullptr, nullptr, DIM, DIM, HID);
    // gates = sh . Wsout^T
    gemm_mma<2,0><<<dim3(20, 8, NEXP), blk, GSMEM>>>(shh, shl, wsoh, wsol, dpar, nullptr, HID, HID, 4*NST);
    // recurrence
    scan_kernel<<<dim3(BATCH, NEXP), 256>>>();
    // out = y . Wout^T
    gemm_mma<3,0><<<dim3(20, 8, NEXP), blk, GSMEM>>>(yh, yl, woth, wotl, nullptr, outp, NST, NST, DIM);
}

// round 6
// speedup vs baseline: 1.3745x; 1.3311x over previous
#include <cuda_runtime.h>
#include <cuda_bf16.h>
#include <cstdint>

#define BATCH 8
#define SEQ   2048
#define DIM   1024
#define NST   256
#define HID   512
#define NEXP  8
#define NTOK  (BATCH*SEQ)   // 16384

// ---------------- device scratch (static, allocation-free) ----------------
__device__ float g_u [NTOK*NST];
__device__ float g_sh[NTOK*HID];
__device__ float g_a [NTOK*NST], g_bu[NTOK*NST], g_c[NTOK*NST], g_sk[NTOK*NST];
__device__ float g_y [NTOK*NST];
__device__ int g_list[NTOK];
__device__ int g_tileCnt[64][NEXP];
__device__ int g_tileOff[64][NEXP];
__device__ int g_eBase[NEXP];
__device__ int g_cnt[NEXP];
__device__ int g_beOff[BATCH][NEXP];
__device__ int g_beCnt[BATCH][NEXP];

__device__ __forceinline__ float sigmoidf_(float x){ return 1.f/(1.f+__expf(-x)); }

__device__ __forceinline__ uint32_t smem_u32(const void* p){
    uint32_t a;
    asm("{ .reg .u64 t; cvta.to.shared.u64 t, %1; cvt.u32.u64 %0, t; }" : "=r"(a) : "l"(p));
    return a;
}
__device__ __forceinline__ void ldsm_x4(uint32_t* r, uint32_t addr){
    asm volatile("ldmatrix.sync.aligned.m8n8.x4.shared.b16 {%0,%1,%2,%3}, [%4];"
        : "=r"(r[0]),"=r"(r[1]),"=r"(r[2]),"=r"(r[3]) : "r"(addr));
}
__device__ __forceinline__ void mma16816(float* d, const uint32_t* a, uint32_t b0, uint32_t b1){
    asm volatile("mma.sync.aligned.m16n8k16.row.col.f32.bf16.bf16.f32 "
        "{%0,%1,%2,%3}, {%4,%5,%6,%7}, {%8,%9}, {%0,%1,%2,%3};"
        : "+f"(d[0]),"+f"(d[1]),"+f"(d[2]),"+f"(d[3])
        : "r"(a[0]),"r"(a[1]),"r"(a[2]),"r"(a[3]), "r"(b0),"r"(b1));
}
// split fp32x4 -> bf16 hi (uint2) + bf16 lo residual (uint2)
__device__ __forceinline__ void cvt4(float4 v, uint2& hi, uint2& lo){
    __nv_bfloat162 h0 = __floats2bfloat162_rn(v.x, v.y);
    __nv_bfloat162 h1 = __floats2bfloat162_rn(v.z, v.w);
    float r0 = v.x - __bfloat162float(__low2bfloat16 (h0));
    float r1 = v.y - __bfloat162float(__high2bfloat16(h0));
    float r2 = v.z - __bfloat162float(__low2bfloat16 (h1));
    float r3 = v.w - __bfloat162float(__high2bfloat16(h1));
    __nv_bfloat162 l0 = __floats2bfloat162_rn(r0, r1);
    __nv_bfloat162 l1 = __floats2bfloat162_rn(r2, r3);
    hi = make_uint2(*reinterpret_cast<uint32_t*>(&h0), *reinterpret_cast<uint32_t*>(&h1));
    lo = make_uint2(*reinterpret_cast<uint32_t*>(&l0), *reinterpret_cast<uint32_t*>(&l1));
}
__device__ __forceinline__ int route_of(int tokid){
    unsigned x = (unsigned)tokid;
    x ^= x >> 16; x *= 2246822507u;
    x ^= x >> 13; x *= 3266489909u;
    x ^= x >> 16;
    return (int)(x & 7u);
}

// ---------------- deterministic routing (count / offset / place) ----------
__global__ void count_kernel(const int* __restrict__ tok){
    int blk = blockIdx.x, tid = threadIdx.x, wid = tid>>5, lane = tid&31;
    int r = route_of(tok[blk*256 + tid]);
    __shared__ int wcnt[8][8];
    unsigned m[8];
    #pragma unroll
    for (int e = 0; e < 8; e++) m[e] = __ballot_sync(0xffffffffu, r == e);
    if (lane < 8) wcnt[wid][lane] = __popc(m[lane]);
    __syncthreads();
    if (tid < 8){
        int s = 0;
        #pragma unroll
        for (int w = 0; w < 8; w++) s += wcnt[w][tid];
        g_tileCnt[blk][tid] = s;
    }
}
__global__ void offset_kernel(){
    __shared__ int tot[8];
    int tid = threadIdx.x;
    if (tid < 8){
        int run = 0;
        for (int t = 0; t < 64; t++){ g_tileOff[t][tid] = run; run += g_tileCnt[t][tid]; }
        tot[tid] = run;
    }
    __syncthreads();
    if (tid == 0){
        int base = 0;
        for (int e = 0; e < 8; e++){ g_eBase[e] = base; g_cnt[e] = tot[e]; base += tot[e]; }
    }
    __syncthreads();
    if (tid < 8){
        for (int t = 0; t < 64; t++) g_tileOff[t][tid] += g_eBase[tid];
        for (int b = 0; b < 8; b++){
            int s = 0;
            for (int k = 0; k < 8; k++) s += g_tileCnt[b*8+k][tid];
            g_beOff[b][tid] = g_tileOff[b*8][tid];
            g_beCnt[b][tid] = s;
        }
    }
}
__global__ void place_kernel(const int* __restrict__ tok){
    int blk = blockIdx.x, tid = threadIdx.x, wid = tid>>5, lane = tid&31;
    int t = blk*256 + tid;
    int r = route_of(tok[t]);
    __shared__ int wcnt[8][8];
    unsigned m[8];
    #pragma unroll
    for (int e = 0; e < 8; e++) m[e] = __ballot_sync(0xffffffffu, r == e);
    if (lane < 8) wcnt[wid][lane] = __popc(m[lane]);
    __syncthreads();
    int base = 0;
    for (int w = 0; w < wid; w++) base += wcnt[w][r];
    int rank = base + __popc(m[r] & ((1u << lane) - 1u));
    g_list[g_tileOff[blk][r] + rank] = t;
}

// ---------------- grouped GEMM: 128x64 tile, bf16x3 mma, 2 CTAs/SM --------
// C = A . W[e]^T ; fp32 operands split-converted in-loop.
// MODE: 0 u, 1 silu->sh, 2 gates, 3 out proj.  GATHER: A row via g_list
#define SSTR   80                 // 32 bf16 padded to 40 (80 B)
#define ATILE  (128*SSTR)         // 10240
#define BTILE  (64*SSTR)          // 5120
// layout: Ah | Al | Bh | Bl  = 2*ATILE + 2*BTILE = 30720 B

template<int MODE, int GATHER>
__global__ void __launch_bounds__(256, 2)
gemm_mma(const float* __restrict__ A, const float* __restrict__ Wt,
         const float* __restrict__ dparam, float* __restrict__ outp,
         int lda, int K, int nout)
{
    const int e   = blockIdx.z;
    const int cnt = g_cnt[e];
    const int m0  = blockIdx.x * 128;
    if (m0 >= cnt) return;
    const int n0  = blockIdx.y * 64;
    const int posBase = g_eBase[e];
    const float* __restrict__ W = Wt + (size_t)e * nout * K;

    __shared__ __align__(16) char sm[2*ATILE + 2*BTILE];
    __shared__ int s_row[128];

    const int tid  = threadIdx.x;
    const int wid  = tid >> 5;
    const int lane = tid & 31;

    if (tid < 128){
        int m  = m0 + tid;
        int mm = m < cnt ? m : cnt - 1;
        s_row[tid] = GATHER ? g_list[posBase + mm] : (posBase + mm);
    }
    __syncthreads();

    // loader: lrow = tid>>3 (0..31), lk = (tid&7)*4 floats
    const int lrow = tid >> 3;
    const int lk   = (tid & 7) * 4;
    const float* aptr[4];
    #pragma unroll
    for (int it = 0; it < 4; it++)
        aptr[it] = A + (size_t)s_row[lrow + it*32]*lda + lk;
    const float* wptr[2];
    #pragma unroll
    for (int it = 0; it < 2; it++)
        wptr[it] = W + (size_t)(n0 + lrow + it*32)*K + lk;
    const int soff = lrow*SSTR + lk*2;   // byte offset within a tile

    const uint32_t sb = smem_u32(sm);
    const int wm = wid & 3, wn = wid >> 2;
    const uint32_t a_base = sb + (uint32_t)((wm*32 + (lane & 15))*SSTR + (lane >> 4)*16);
    const uint32_t b_base = sb + 2*ATILE +
        (uint32_t)((wn*32 + (lane >> 4)*8 + (lane & 7))*SSTR + ((lane >> 3) & 1)*16);

    float acc[2][4][4];
    #pragma unroll
    for (int mi=0;mi<2;mi++)
        #pragma unroll
        for (int ni=0;ni<4;ni++)
            #pragma unroll
            for (int q=0;q<4;q++) acc[mi][ni][q]=0.f;

    const int NC = K >> 5;
    float4 pa[4], pb[2];
    #pragma unroll
    for (int it = 0; it < 4; it++) pa[it] = *(const float4*)aptr[it];
    #pragma unroll
    for (int it = 0; it < 2; it++) pb[it] = *(const float4*)wptr[it];

    for (int c = 0; c < NC; c++){
        __syncthreads();
        #pragma unroll
        for (int it = 0; it < 4; it++){
            uint2 hi, lo;
            int off = soff + it*32*SSTR;
            cvt4(pa[it], hi, lo);
            *(uint2*)(sm + off)         = hi;
            *(uint2*)(sm + ATILE + off) = lo;
        }
        #pragma unroll
        for (int it = 0; it < 2; it++){
            uint2 hi, lo;
            int off = soff + it*32*SSTR;
            cvt4(pb[it], hi, lo);
            *(uint2*)(sm + 2*ATILE + off)         = hi;
            *(uint2*)(sm + 2*ATILE + BTILE + off) = lo;
        }
        __syncthreads();
        if (c + 1 < NC){
            const int k1 = (c + 1) << 5;
            #pragma unroll
            for (int it = 0; it < 4; it++) pa[it] = *(const float4*)(aptr[it] + k1);
            #pragma unroll
            for (int it = 0; it < 2; it++) pb[it] = *(const float4*)(wptr[it] + k1);
        }
        #pragma unroll
        for (int ks = 0; ks < 2; ks++){
            uint32_t ah[2][4], al[2][4], bh[2][4], bl[2][4];
            #pragma unroll
            for (int mi = 0; mi < 2; mi++){
                uint32_t ad = a_base + mi*16*SSTR + ks*32;
                ldsm_x4(ah[mi], ad);
                ldsm_x4(al[mi], ad + ATILE);
            }
            #pragma unroll
            for (int np = 0; np < 2; np++){
                uint32_t bd = b_base + np*16*SSTR + ks*32;
                ldsm_x4(bh[np], bd);
                ldsm_x4(bl[np], bd + BTILE);
            }
            #pragma unroll
            for (int mi = 0; mi < 2; mi++)
                #pragma unroll
                for (int ni = 0; ni < 4; ni++){
                    const int np = ni >> 1, h = (ni & 1)*2;
                    mma16816(acc[mi][ni], ah[mi], bh[np][h], bh[np][h+1]);
                    mma16816(acc[mi][ni], ah[mi], bl[np][h], bl[np][h+1]);
                    mma16816(acc[mi][ni], al[mi], bh[np][h], bh[np][h+1]);
                }
        }
    }

    // ---- epilogue
    const int sec = (MODE == 2) ? (n0 >> 8) : 0;
    #pragma unroll
    for (int mi = 0; mi < 2; mi++){
        const int rt0 = wm*32 + mi*16 + (lane >> 2);
        #pragma unroll
        for (int hf = 0; hf < 2; hf++){
            const int rt = rt0 + hf*8;
            const int m  = m0 + rt;
            if (m >= cnt) continue;
            const int pos = posBase + m;
            #pragma unroll
            for (int ni = 0; ni < 4; ni++){
                float v0 = acc[mi][ni][hf*2], v1 = acc[mi][ni][hf*2+1];
                const int col = n0 + wn*32 + (ni>>1)*16 + (ni&1)*8 + (lane&3)*2;
                if (MODE == 0){
                    *(float2*)(g_u + (size_t)pos*NST + col) = make_float2(v0, v1);
                } else if (MODE == 1){
                    *(float2*)(g_sh + (size_t)pos*HID + col) =
                        make_float2(v0*sigmoidf_(v0), v1*sigmoidf_(v1));
                } else if (MODE == 2){
                    const int off = col & 255;
                    const size_t base = (size_t)pos*NST + off;
                    if (sec == 0){
                        *(float2*)(g_a + base) = make_float2(sigmoidf_(v0), sigmoidf_(v1));
                    } else if (sec == 1){
                        float2 u2 = *(const float2*)(g_u + base);
                        *(float2*)(g_bu + base) = make_float2(tanhf(v0)*u2.x, tanhf(v1)*u2.y);
                    } else if (sec == 2){
                        *(float2*)(g_c + base) = make_float2(tanhf(v0), tanhf(v1));
                    } else {
                        float2 u2 = *(const float2*)(g_u + base);
                        float2 d2 = *(const float2*)(dparam + e*NST + off);
                        *(float2*)(g_sk + base) =
                            make_float2(sigmoidf_(v0)*d2.x*u2.x, sigmoidf_(v1)*d2.y*u2.y);
                    }
                } else {
                    const int tok = g_list[pos];
                    *(float2*)(outp + (size_t)tok*DIM + col) = make_float2(v0, v1);
                }
            }
        }
    }
}

// ---------------- sequential scan, compact streaming ----------------
__global__ void __launch_bounds__(256)
scan_kernel()
{
    const int b = blockIdx.x, e = blockIdx.y, tid = threadIdx.x;
    const int pos0 = g_beOff[b][e];
    const int n    = g_beCnt[b][e];

    float a[2][4], bu[2][4], cc[2][4], sk[2][4];
    #pragma unroll
    for (int j = 0; j < 4; j++){
        bool v = j < n;
        size_t idx = ((size_t)(pos0 + (v ? j : 0)))*NST + tid;
        a [0][j] = v ? g_a [idx] : 0.f;
        bu[0][j] = v ? g_bu[idx] : 0.f;
        cc[0][j] = v ? g_c [idx] : 0.f;
        sk[0][j] = v ? g_sk[idx] : 0.f;
    }

    float h = 0.f;
    int cur = 0;
    for (int base = 0; base < n; base += 4){
        const int nxt = cur ^ 1;
        #pragma unroll
        for (int j = 0; j < 4; j++){
            int i = base + 4 + j;
            if (i < n){
                size_t idx = ((size_t)(pos0 + i))*NST + tid;
                a [nxt][j] = g_a [idx];
                bu[nxt][j] = g_bu[idx];
                cc[nxt][j] = g_c [idx];
                sk[nxt][j] = g_sk[idx];
            }
        }
        #pragma unroll
        for (int j = 0; j < 4; j++){
            int i = base + j;
            if (i < n){
                h = fmaf(a[cur][j], h, bu[cur][j]);
                float y = fmaf(cc[cur][j], h, sk[cur][j]);
                g_y[((size_t)(pos0 + i))*NST + tid] = y;
            }
        }
        cur = nxt;
    }
}

// ---------------- launch ----------------
extern "C" void kernel_launch(void* const* d_in, const int* in_sizes, int n_in,
                              void* d_out, int out_size)
{
    const float* x     = (const float*)d_in[0];
    const int*   tok   = (const int*)  d_in[1];
    const float* Win   = (const float*)d_in[2];
    const float* Wsin  = (const float*)d_in[3];
    const float* Wsout = (const float*)d_in[4];
    const float* Wout  = (const float*)d_in[5];
    const float* dpar  = (const float*)d_in[6];
    float* outp = (float*)d_out;
    (void)in_sizes; (void)n_in; (void)out_size;

    float *u, *sh, *y;
    cudaGetSymbolAddress((void**)&u,  g_u);
    cudaGetSymbolAddress((void**)&sh, g_sh);
    cudaGetSymbolAddress((void**)&y,  g_y);

    // deterministic routing
    count_kernel <<<64, 256>>>(tok);
    offset_kernel<<<1, 256>>>();
    place_kernel <<<64, 256>>>(tok);

    dim3 blk(256);
    // u = x . Win^T            (K=1024, nout=256)
    gemm_mma<0,1><<<dim3(20, 4,  NEXP), blk>>>(x,  Win,   nullptr, nullptr, DIM, DIM, NST);
    // sh = silu(x . Wsin^T)    (K=1024, nout=512)
    gemm_mma<1,1><<<dim3(20, 8,  NEXP), blk>>>(x,  Wsin,  nullptr, nullptr, DIM, DIM, HID);
    // gates = sh . Wsout^T     (K=512,  nout=1024)
    gemm_mma<2,0><<<dim3(20, 16, NEXP), blk>>>(sh, Wsout, dpar,    nullptr, HID, HID, 4*NST);
    // recurrence
    scan_kernel<<<dim3(BATCH, NEXP), 256>>>();
    // out = y . Wout^T         (K=256,  nout=1024)
    gemm_mma<3,0><<<dim3(20, 16, NEXP), blk>>>(y,  Wout,  nullptr, outp,    NST, NST, DIM);
}

// round 7
// speedup vs baseline: 1.5349x; 1.1167x over previous
#include <cuda_runtime.h>
#include <cuda_fp16.h>
#include <cstdint>

#define BATCH 8
#define SEQ   2048
#define DIM   1024
#define NST   256
#define HID   512
#define NEXP  8
#define NTOK  (BATCH*SEQ)   // 16384

// ---------------- device scratch (static, allocation-free) ----------------
__device__ float g_u [NTOK*NST];
__device__ float g_sh[NTOK*HID];
__device__ float g_a [NTOK*NST], g_bu[NTOK*NST], g_c[NTOK*NST], g_sk[NTOK*NST];
__device__ float g_y [NTOK*NST];
__device__ int g_list[NTOK];
__device__ int g_tileCnt[64][NEXP];
__device__ int g_tileOff[64][NEXP];
__device__ int g_eBase[NEXP];
__device__ int g_cnt[NEXP];
__device__ int g_beOff[BATCH][NEXP];
__device__ int g_beCnt[BATCH][NEXP];

__device__ __forceinline__ float sigmoidf_(float x){ return 1.f/(1.f+__expf(-x)); }

__device__ __forceinline__ uint32_t smem_u32(const void* p){
    uint32_t a;
    asm("{ .reg .u64 t; cvta.to.shared.u64 t, %1; cvt.u32.u64 %0, t; }" : "=r"(a) : "l"(p));
    return a;
}
__device__ __forceinline__ void ldsm_x4(uint32_t* r, uint32_t addr){
    asm volatile("ldmatrix.sync.aligned.m8n8.x4.shared.b16 {%0,%1,%2,%3}, [%4];"
        : "=r"(r[0]),"=r"(r[1]),"=r"(r[2]),"=r"(r[3]) : "r"(addr));
}
__device__ __forceinline__ void mma16816h(float* d, const uint32_t* a, uint32_t b0, uint32_t b1){
    asm volatile("mma.sync.aligned.m16n8k16.row.col.f32.f16.f16.f32 "
        "{%0,%1,%2,%3}, {%4,%5,%6,%7}, {%8,%9}, {%0,%1,%2,%3};"
        : "+f"(d[0]),"+f"(d[1]),"+f"(d[2]),"+f"(d[3])
        : "r"(a[0]),"r"(a[1]),"r"(a[2]),"r"(a[3]), "r"(b0),"r"(b1));
}
// split fp32x4 -> fp16 hi (uint2) + fp16 lo residual (uint2)
__device__ __forceinline__ void cvt4h(float4 v, uint2& hi, uint2& lo){
    __half2 h0 = __floats2half2_rn(v.x, v.y);
    __half2 h1 = __floats2half2_rn(v.z, v.w);
    float r0 = v.x - __half2float(__low2half (h0));
    float r1 = v.y - __half2float(__high2half(h0));
    float r2 = v.z - __half2float(__low2half (h1));
    float r3 = v.w - __half2float(__high2half(h1));
    __half2 l0 = __floats2half2_rn(r0, r1);
    __half2 l1 = __floats2half2_rn(r2, r3);
    hi = make_uint2(*reinterpret_cast<uint32_t*>(&h0), *reinterpret_cast<uint32_t*>(&h1));
    lo = make_uint2(*reinterpret_cast<uint32_t*>(&l0), *reinterpret_cast<uint32_t*>(&l1));
}
// fp32x4 -> fp16 hi only
__device__ __forceinline__ void cvt4s(float4 v, uint2& hi){
    __half2 h0 = __floats2half2_rn(v.x, v.y);
    __half2 h1 = __floats2half2_rn(v.z, v.w);
    hi = make_uint2(*reinterpret_cast<uint32_t*>(&h0), *reinterpret_cast<uint32_t*>(&h1));
}
__device__ __forceinline__ int route_of(int tokid){
    unsigned x = (unsigned)tokid;
    x ^= x >> 16; x *= 2246822507u;
    x ^= x >> 13; x *= 3266489909u;
    x ^= x >> 16;
    return (int)(x & 7u);
}

// ---------------- deterministic routing (count / offset / place) ----------
__global__ void count_kernel(const int* __restrict__ tok){
    int blk = blockIdx.x, tid = threadIdx.x, wid = tid>>5, lane = tid&31;
    int r = route_of(tok[blk*256 + tid]);
    __shared__ int wcnt[8][8];
    unsigned m[8];
    #pragma unroll
    for (int e = 0; e < 8; e++) m[e] = __ballot_sync(0xffffffffu, r == e);
    if (lane < 8) wcnt[wid][lane] = __popc(m[lane]);
    __syncthreads();
    if (tid < 8){
        int s = 0;
        #pragma unroll
        for (int w = 0; w < 8; w++) s += wcnt[w][tid];
        g_tileCnt[blk][tid] = s;
    }
}
__global__ void offset_kernel(){
    __shared__ int tot[8];
    int tid = threadIdx.x;
    if (tid < 8){
        int run = 0;
        for (int t = 0; t < 64; t++){ g_tileOff[t][tid] = run; run += g_tileCnt[t][tid]; }
        tot[tid] = run;
    }
    __syncthreads();
    if (tid == 0){
        int base = 0;
        for (int e = 0; e < 8; e++){ g_eBase[e] = base; g_cnt[e] = tot[e]; base += tot[e]; }
    }
    __syncthreads();
    if (tid < 8){
        for (int t = 0; t < 64; t++) g_tileOff[t][tid] += g_eBase[tid];
        for (int b = 0; b < 8; b++){
            int s = 0;
            for (int k = 0; k < 8; k++) s += g_tileCnt[b*8+k][tid];
            g_beOff[b][tid] = g_tileOff[b*8][tid];
            g_beCnt[b][tid] = s;
        }
    }
}
__global__ void place_kernel(const int* __restrict__ tok){
    int blk = blockIdx.x, tid = threadIdx.x, wid = tid>>5, lane = tid&31;
    int t = blk*256 + tid;
    int r = route_of(tok[t]);
    __shared__ int wcnt[8][8];
    unsigned m[8];
    #pragma unroll
    for (int e = 0; e < 8; e++) m[e] = __ballot_sync(0xffffffffu, r == e);
    if (lane < 8) wcnt[wid][lane] = __popc(m[lane]);
    __syncthreads();
    int base = 0;
    for (int w = 0; w < wid; w++) base += wcnt[w][r];
    int rank = base + __popc(m[r] & ((1u << lane) - 1u));
    g_list[g_tileOff[blk][r] + rank] = t;
}

// ---------------- grouped GEMM: 128x64 tile, fp16x2 mma, 2 CTAs/SM --------
// C = A . W[e]^T ; A split to fp16 hi+lo, W rounded to fp16 (err ~2^-12).
// MODE: 0 u, 1 silu->sh, 2 gates, 3 out proj.  GATHER: A row via g_list
#define SSTR   80                 // 32 fp16 padded to 40 (80 B)
#define ATILE  (128*SSTR)         // 10240
#define BTILE  (64*SSTR)          // 5120
// layout: Ah | Al | Bh  = 2*ATILE + BTILE = 25600 B

template<int MODE, int GATHER>
__global__ void __launch_bounds__(256, 2)
gemm_mma(const float* __restrict__ A, const float* __restrict__ Wt,
         const float* __restrict__ dparam, float* __restrict__ outp,
         int lda, int K, int nout)
{
    const int e   = blockIdx.z;
    const int cnt = g_cnt[e];
    const int m0  = blockIdx.x * 128;
    if (m0 >= cnt) return;
    const int n0  = blockIdx.y * 64;
    const int posBase = g_eBase[e];
    const float* __restrict__ W = Wt + (size_t)e * nout * K;

    __shared__ __align__(16) char sm[2*ATILE + BTILE];
    __shared__ int s_row[128];

    const int tid  = threadIdx.x;
    const int wid  = tid >> 5;
    const int lane = tid & 31;

    if (tid < 128){
        int m  = m0 + tid;
        int mm = m < cnt ? m : cnt - 1;
        s_row[tid] = GATHER ? g_list[posBase + mm] : (posBase + mm);
    }
    __syncthreads();

    // loader: lrow = tid>>3 (0..31), lk = (tid&7)*4 floats
    const int lrow = tid >> 3;
    const int lk   = (tid & 7) * 4;
    const float* aptr[4];
    #pragma unroll
    for (int it = 0; it < 4; it++)
        aptr[it] = A + (size_t)s_row[lrow + it*32]*lda + lk;
    const float* wptr[2];
    #pragma unroll
    for (int it = 0; it < 2; it++)
        wptr[it] = W + (size_t)(n0 + lrow + it*32)*K + lk;
    const int soff = lrow*SSTR + lk*2;   // byte offset within a tile

    const uint32_t sb = smem_u32(sm);
    const int wm = wid & 3, wn = wid >> 2;
    const uint32_t a_base = sb + (uint32_t)((wm*32 + (lane & 15))*SSTR + (lane >> 4)*16);
    const uint32_t b_base = sb + 2*ATILE +
        (uint32_t)((wn*32 + (lane >> 4)*8 + (lane & 7))*SSTR + ((lane >> 3) & 1)*16);

    float acc[2][4][4];
    #pragma unroll
    for (int mi=0;mi<2;mi++)
        #pragma unroll
        for (int ni=0;ni<4;ni++)
            #pragma unroll
            for (int q=0;q<4;q++) acc[mi][ni][q]=0.f;

    const int NC = K >> 5;
    float4 pa[4], pb[2];
    #pragma unroll
    for (int it = 0; it < 4; it++) pa[it] = *(const float4*)aptr[it];
    #pragma unroll
    for (int it = 0; it < 2; it++) pb[it] = *(const float4*)wptr[it];

    for (int c = 0; c < NC; c++){
        __syncthreads();
        #pragma unroll
        for (int it = 0; it < 4; it++){
            uint2 hi, lo;
            int off = soff + it*32*SSTR;
            cvt4h(pa[it], hi, lo);
            *(uint2*)(sm + off)         = hi;
            *(uint2*)(sm + ATILE + off) = lo;
        }
        #pragma unroll
        for (int it = 0; it < 2; it++){
            uint2 hi;
            int off = soff + it*32*SSTR;
            cvt4s(pb[it], hi);
            *(uint2*)(sm + 2*ATILE + off) = hi;
        }
        __syncthreads();
        if (c + 1 < NC){
            const int k1 = (c + 1) << 5;
            #pragma unroll
            for (int it = 0; it < 4; it++) pa[it] = *(const float4*)(aptr[it] + k1);
            #pragma unroll
            for (int it = 0; it < 2; it++) pb[it] = *(const float4*)(wptr[it] + k1);
        }
        #pragma unroll
        for (int ks = 0; ks < 2; ks++){
            uint32_t ah[2][4], al[2][4], bh[2][4];
            #pragma unroll
            for (int mi = 0; mi < 2; mi++){
                uint32_t ad = a_base + mi*16*SSTR + ks*32;
                ldsm_x4(ah[mi], ad);
                ldsm_x4(al[mi], ad + ATILE);
            }
            #pragma unroll
            for (int np = 0; np < 2; np++){
                uint32_t bd = b_base + np*16*SSTR + ks*32;
                ldsm_x4(bh[np], bd);
            }
            #pragma unroll
            for (int mi = 0; mi < 2; mi++)
                #pragma unroll
                for (int ni = 0; ni < 4; ni++){
                    const int np = ni >> 1, h = (ni & 1)*2;
                    mma16816h(acc[mi][ni], ah[mi], bh[np][h], bh[np][h+1]);
                    mma16816h(acc[mi][ni], al[mi], bh[np][h], bh[np][h+1]);
                }
        }
    }

    // ---- epilogue
    const int sec = (MODE == 2) ? (n0 >> 8) : 0;
    #pragma unroll
    for (int mi = 0; mi < 2; mi++){
        const int rt0 = wm*32 + mi*16 + (lane >> 2);
        #pragma unroll
        for (int hf = 0; hf < 2; hf++){
            const int rt = rt0 + hf*8;
            const int m  = m0 + rt;
            if (m >= cnt) continue;
            const int pos = posBase + m;
            #pragma unroll
            for (int ni = 0; ni < 4; ni++){
                float v0 = acc[mi][ni][hf*2], v1 = acc[mi][ni][hf*2+1];
                const int col = n0 + wn*32 + (ni>>1)*16 + (ni&1)*8 + (lane&3)*2;
                if (MODE == 0){
                    *(float2*)(g_u + (size_t)pos*NST + col) = make_float2(v0, v1);
                } else if (MODE == 1){
                    *(float2*)(g_sh + (size_t)pos*HID + col) =
                        make_float2(v0*sigmoidf_(v0), v1*sigmoidf_(v1));
                } else if (MODE == 2){
                    const int off = col & 255;
                    const size_t base = (size_t)pos*NST + off;
                    if (sec == 0){
                        *(float2*)(g_a + base) = make_float2(sigmoidf_(v0), sigmoidf_(v1));
                    } else if (sec == 1){
                        float2 u2 = *(const float2*)(g_u + base);
                        *(float2*)(g_bu + base) = make_float2(tanhf(v0)*u2.x, tanhf(v1)*u2.y);
                    } else if (sec == 2){
                        *(float2*)(g_c + base) = make_float2(tanhf(v0), tanhf(v1));
                    } else {
                        float2 u2 = *(const float2*)(g_u + base);
                        float2 d2 = *(const float2*)(dparam + e*NST + off);
                        *(float2*)(g_sk + base) =
                            make_float2(sigmoidf_(v0)*d2.x*u2.x, sigmoidf_(v1)*d2.y*u2.y);
                    }
                } else {
                    const int tok = g_list[pos];
                    *(float2*)(outp + (size_t)tok*DIM + col) = make_float2(v0, v1);
                }
            }
        }
    }
}

// ---------------- sequential scan, compact streaming ----------------
__global__ void __launch_bounds__(256)
scan_kernel()
{
    const int b = blockIdx.x, e = blockIdx.y, tid = threadIdx.x;
    const int pos0 = g_beOff[b][e];
    const int n    = g_beCnt[b][e];

    float a[2][4], bu[2][4], cc[2][4], sk[2][4];
    #pragma unroll
    for (int j = 0; j < 4; j++){
        bool v = j < n;
        size_t idx = ((size_t)(pos0 + (v ? j : 0)))*NST + tid;
        a [0][j] = v ? g_a [idx] : 0.f;
        bu[0][j] = v ? g_bu[idx] : 0.f;
        cc[0][j] = v ? g_c [idx] : 0.f;
        sk[0][j] = v ? g_sk[idx] : 0.f;
    }

    float h = 0.f;
    int cur = 0;
    for (int base = 0; base < n; base += 4){
        const int nxt = cur ^ 1;
        #pragma unroll
        for (int j = 0; j < 4; j++){
            int i = base + 4 + j;
            if (i < n){
                size_t idx = ((size_t)(pos0 + i))*NST + tid;
                a [nxt][j] = g_a [idx];
                bu[nxt][j] = g_bu[idx];
                cc[nxt][j] = g_c [idx];
                sk[nxt][j] = g_sk[idx];
            }
        }
        #pragma unroll
        for (int j = 0; j < 4; j++){
            int i = base + j;
            if (i < n){
                h = fmaf(a[cur][j], h, bu[cur][j]);
                float y = fmaf(cc[cur][j], h, sk[cur][j]);
                g_y[((size_t)(pos0 + i))*NST + tid] = y;
            }
        }
        cur = nxt;
    }
}

// ---------------- launch ----------------
extern "C" void kernel_launch(void* const* d_in, const int* in_sizes, int n_in,
                              void* d_out, int out_size)
{
    const float* x     = (const float*)d_in[0];
    const int*   tok   = (const int*)  d_in[1];
    const float* Win   = (const float*)d_in[2];
    const float* Wsin  = (const float*)d_in[3];
    const float* Wsout = (const float*)d_in[4];
    const float* Wout  = (const float*)d_in[5];
    const float* dpar  = (const float*)d_in[6];
    float* outp = (float*)d_out;
    (void)in_sizes; (void)n_in; (void)out_size;

    float *u, *sh, *y;
    cudaGetSymbolAddress((void**)&u,  g_u);
    cudaGetSymbolAddress((void**)&sh, g_sh);
    cudaGetSymbolAddress((void**)&y,  g_y);

    // deterministic routing
    count_kernel <<<64, 256>>>(tok);
    offset_kernel<<<1, 256>>>();
    place_kernel <<<64, 256>>>(tok);

    dim3 blk(256);
    // u = x . Win^T            (K=1024, nout=256)
    gemm_mma<0,1><<<dim3(20, 4,  NEXP), blk>>>(x,  Win,   nullptr, nullptr, DIM, DIM, NST);
    // sh = silu(x . Wsin^T)    (K=1024, nout=512)
    gemm_mma<1,1><<<dim3(20, 8,  NEXP), blk>>>(x,  Wsin,  nullptr, nullptr, DIM, DIM, HID);
    // gates = sh . Wsout^T     (K=512,  nout=1024)
    gemm_mma<2,0><<<dim3(20, 16, NEXP), blk>>>(sh, Wsout, dpar,    nullptr, HID, HID, 4*NST);
    // recurrence
    scan_kernel<<<dim3(BATCH, NEXP), 256>>>();
    // out = y . Wout^T         (K=256,  nout=1024)
    gemm_mma<3,0><<<dim3(20, 16, NEXP), blk>>>(y,  Wout,  nullptr, outp,    NST, NST, DIM);
}